// round 3
// baseline (speedup 1.0000x reference)
#include <cuda_runtime.h>
#include <cuda_bf16.h>
#include <cstdint>

// ---------------------------------------------------------------------------
// FactorizedSoftmaxV2: adaptive-softmax NLL
//   nll[t] = (lse3 - s_cluster) + (log sumexp(tail) - z_target)
// Strategy: bucket tokens by cluster, per-cluster tiled GEMM fused with
// row-wise sum-of-exp (no max pass needed: |z| < ~4 by construction) and
// target-logit capture. Inner product uses packed fma.rn.f32x2.
// NOTES:
//  - vocab=50257 is ODD -> logits rows only 4B-aligned; scalar loads there.
//  - y is INT32 (JAX x64-disabled coerces the requested int64 to int32).
// ---------------------------------------------------------------------------

#define MAX_TOK 4096
#define N_CLUSTERS 3

__device__ int   g_order[MAX_TOK];
__device__ int   g_counts[N_CLUSTERS];
__device__ int   g_bases[N_CLUSTERS];
__device__ float g_rownll[MAX_TOK];   // lse3 - s_cy  (cluster-head NLL part)
__device__ float g_sumexp[MAX_TOK];   // accumulated sum of exp(tail logits)
__device__ float g_tgt[MAX_TOK];      // tail logit at target column

__device__ __forceinline__ unsigned long long pack2(float lo, float hi) {
    unsigned long long r;
    asm("mov.b64 %0, {%1,%2};" : "=l"(r) : "f"(lo), "f"(hi));
    return r;
}
__device__ __forceinline__ void fma2(unsigned long long& d,
                                     unsigned long long a,
                                     unsigned long long b) {
    asm("fma.rn.f32x2 %0, %1, %2, %0;" : "+l"(d) : "l"(a), "l"(b));
}
__device__ __forceinline__ float2 unpack2(unsigned long long v) {
    float2 f;
    asm("mov.b64 {%0,%1}, %2;" : "=f"(f.x), "=f"(f.y) : "l"(v));
    return f;
}

__device__ __forceinline__ int cluster_of(int yy) {
    return yy < 20000 ? 0 : (yy < 40000 ? 1 : 2);
}

// ---------------------------------------------------------------------------
// K1: cluster head. One warp per token: 3 dots of length `hidden`,
// log_softmax over 3, store lse3 - s_cy. Also zero per-token accumulators.
// ---------------------------------------------------------------------------
__global__ void k_cluster(const float* __restrict__ x,
                          const int* __restrict__ y,
                          const float* __restrict__ Wc,
                          int n, int hidden) {
    int warp = (blockIdx.x * blockDim.x + threadIdx.x) >> 5;
    int lane = threadIdx.x & 31;
    if (warp >= n) return;
    const float* xr = x + (size_t)warp * hidden;
    float s0 = 0.f, s1 = 0.f, s2 = 0.f;
    for (int k = lane; k < hidden; k += 32) {
        float xv = xr[k];
        s0 += xv * Wc[k];
        s1 += xv * Wc[hidden + k];
        s2 += xv * Wc[2 * hidden + k];
    }
#pragma unroll
    for (int m = 16; m; m >>= 1) {
        s0 += __shfl_xor_sync(0xffffffffu, s0, m);
        s1 += __shfl_xor_sync(0xffffffffu, s1, m);
        s2 += __shfl_xor_sync(0xffffffffu, s2, m);
    }
    if (lane == 0) {
        int cy = cluster_of(y[warp]);
        float mx = fmaxf(s0, fmaxf(s1, s2));
        float lse = logf(expf(s0 - mx) + expf(s1 - mx) + expf(s2 - mx)) + mx;
        float sc = (cy == 0) ? s0 : ((cy == 1) ? s1 : s2);
        g_rownll[warp] = lse - sc;
        g_sumexp[warp] = 0.f;
        g_tgt[warp] = 0.f;
    }
}

// ---------------------------------------------------------------------------
// K2: bucket tokens by cluster (single block).
// ---------------------------------------------------------------------------
__global__ void k_bucket(const int* __restrict__ y, int n) {
    __shared__ int cnt[N_CLUSTERS];
    __shared__ int base[N_CLUSTERS];
    int tid = threadIdx.x;
    if (tid < N_CLUSTERS) cnt[tid] = 0;
    __syncthreads();
    for (int t = tid; t < n; t += blockDim.x)
        atomicAdd(&cnt[cluster_of(y[t])], 1);
    __syncthreads();
    if (tid == 0) {
        int b0 = 0, b1 = cnt[0], b2 = cnt[0] + cnt[1];
        g_counts[0] = cnt[0]; g_counts[1] = cnt[1]; g_counts[2] = cnt[2];
        g_bases[0] = b0; g_bases[1] = b1; g_bases[2] = b2;
        base[0] = b0; base[1] = b1; base[2] = b2;
        cnt[0] = 0; cnt[1] = 0; cnt[2] = 0;
    }
    __syncthreads();
    for (int t = tid; t < n; t += blockDim.x) {
        int c = cluster_of(y[t]);
        int idx = atomicAdd(&cnt[c], 1);
        g_order[base[c] + idx] = t;
    }
}

// ---------------------------------------------------------------------------
// K3: main fused GEMM + sum-of-exp + target capture.
// TM=TN=128, BK=16, 256 threads, 8x8 micro-tile, f32x2 packed FMA.
// grid = (maxColTiles, tokenTiles, 3)
// ---------------------------------------------------------------------------
__global__ __launch_bounds__(256)
void k_main(const float* __restrict__ x,
            const int* __restrict__ y,
            const float* __restrict__ logits,
            int vocab, int hidden) {
    const int c = blockIdx.z;
    const int l = (c == 0) ? 0 : ((c == 1) ? 20000 : 40000);
    const int r = (c == 0) ? 20000 : ((c == 1) ? 40000 : vocab);
    const int ncols = r - l;
    const int col0 = blockIdx.x * 128;
    if (col0 >= ncols) return;
    const int count = g_counts[c];
    const int row0 = blockIdx.y * 128;
    if (row0 >= count) return;
    const int base = g_bases[c];

    __shared__ __align__(16) float xs[16][132];
    __shared__ __align__(16) float ws[16][132];
    __shared__ int stok[128];
    __shared__ int sy[128];

    const int tid = threadIdx.x;

    for (int i = tid; i < 128; i += 256) {
        int rg = row0 + i;
        int t = g_order[base + (rg < count ? rg : 0)];
        stok[i] = t;
        sy[i] = y[t] - l;
    }
    __syncthreads();

    unsigned long long acc[8][4];
#pragma unroll
    for (int i = 0; i < 8; i++)
#pragma unroll
        for (int j = 0; j < 4; j++) acc[i][j] = 0ull;

    const int ty = tid >> 4;
    const int tx = tid & 15;

    // logits tile load indexing (scalar, 8 elems/thread): kk = row, nn = col
    const int w_kk = tid >> 7;          // 0..1 (base k row; +2 each sub-iter)
    const int w_nn = tid & 127;         // 0..127

    for (int k0 = 0; k0 < hidden; k0 += 16) {
        // load x tile (transposed into xs[k][m]) with float4 (x is 16B aligned)
#pragma unroll
        for (int j = 0; j < 2; j++) {
            int idx = tid + j * 256;
            int m = idx >> 2, kq = idx & 3;
            float4 v = *(const float4*)(x + (size_t)stok[m] * hidden + k0 + kq * 4);
            xs[kq * 4 + 0][m] = v.x;
            xs[kq * 4 + 1][m] = v.y;
            xs[kq * 4 + 2][m] = v.z;
            xs[kq * 4 + 3][m] = v.w;
        }
        // load logits tile ws[k][n]: SCALAR loads (vocab odd -> rows only 4B aligned)
        {
            int cg = col0 + w_nn;
            bool ok = cg < ncols;
            const float* src = logits + (size_t)k0 * vocab + (size_t)w_kk * vocab + l + cg;
#pragma unroll
            for (int j = 0; j < 8; j++) {
                ws[w_kk + j * 2][w_nn] = ok ? src[(size_t)(j * 2) * vocab] : 0.f;
            }
        }
        __syncthreads();

#pragma unroll
        for (int k = 0; k < 16; k++) {
            float4 a0 = *(const float4*)&xs[k][ty * 8];
            float4 a1 = *(const float4*)&xs[k][ty * 8 + 4];
            float4 b0 = *(const float4*)&ws[k][tx * 8];
            float4 b1 = *(const float4*)&ws[k][tx * 8 + 4];
            unsigned long long bp0 = pack2(b0.x, b0.y);
            unsigned long long bp1 = pack2(b0.z, b0.w);
            unsigned long long bp2 = pack2(b1.x, b1.y);
            unsigned long long bp3 = pack2(b1.z, b1.w);
            float av[8] = {a0.x, a0.y, a0.z, a0.w, a1.x, a1.y, a1.z, a1.w};
#pragma unroll
            for (int i = 0; i < 8; i++) {
                unsigned long long ap = pack2(av[i], av[i]);
                fma2(acc[i][0], ap, bp0);
                fma2(acc[i][1], ap, bp1);
                fma2(acc[i][2], ap, bp2);
                fma2(acc[i][3], ap, bp3);
            }
        }
        __syncthreads();
    }

    // epilogue: per-row sum of exp + target capture
#pragma unroll
    for (int i = 0; i < 8; i++) {
        int rl = ty * 8 + i;
        int rg = row0 + rl;
        bool rv = rg < count;
        int t = stok[rl];
        int ytc = sy[rl];
        float rowsum = 0.f;
#pragma unroll
        for (int jp = 0; jp < 4; jp++) {
            float2 v = unpack2(acc[i][jp]);
            int cl0 = col0 + tx * 8 + jp * 2;
            if (cl0 < ncols) {
                rowsum += __expf(v.x);
                if (rv && cl0 == ytc) g_tgt[t] = v.x;
            }
            if (cl0 + 1 < ncols) {
                rowsum += __expf(v.y);
                if (rv && cl0 + 1 == ytc) g_tgt[t] = v.y;
            }
        }
#pragma unroll
        for (int m = 8; m; m >>= 1)
            rowsum += __shfl_xor_sync(0xffffffffu, rowsum, m);
        if (tx == 0 && rv) atomicAdd(&g_sumexp[t], rowsum);
    }
}

// ---------------------------------------------------------------------------
// K4: finalize. nll = rownll + log(sumexp) - z_tgt
// ---------------------------------------------------------------------------
__global__ void k_final(float* __restrict__ out, int n) {
    int t = blockIdx.x * blockDim.x + threadIdx.x;
    if (t >= n) return;
    out[t] = g_rownll[t] + logf(g_sumexp[t]) - g_tgt[t];
}

extern "C" void kernel_launch(void* const* d_in, const int* in_sizes, int n_in,
                              void* d_out, int out_size) {
    const float* x = (const float*)d_in[0];
    const int* y = (const int*)d_in[1];
    const float* Wc = (const float*)d_in[2];
    const float* logits = (const float*)d_in[3];
    float* out = (float*)d_out;

    int n = in_sizes[1];                 // 4096 tokens
    int hidden = in_sizes[0] / n;        // 1024
    int vocab = in_sizes[3] / hidden;    // 50257

    // K1: cluster head (1 warp / token)
    k_cluster<<<(n + 7) / 8, 256>>>(x, y, Wc, n, hidden);
    // K2: bucket
    k_bucket<<<1, 1024>>>(y, n);
    // K3: main fused GEMM (max slice = 20000 cols -> 157 col tiles)
    int maxcols = 20000 > (vocab - 40000) ? 20000 : (vocab - 40000);
    dim3 grid((maxcols + 127) / 128, (n + 127) / 128, 3);
    k_main<<<grid, 256>>>(x, y, logits, vocab, hidden);
    // K4: finalize
    k_final<<<(n + 255) / 256, 256>>>(out, n);
}

// round 5
// speedup vs baseline: 3.8912x; 3.8912x over previous
#include <cuda_runtime.h>
#include <cuda_bf16.h>
#include <cstdint>

// ---------------------------------------------------------------------------
// FactorizedSoftmaxV2 via mma.sync bf16 (HMMA; tcgen05 PTX is rejected because
// the harness compiles at virtual arch compute_103, not compute_103a).
//   nll[t] = (lse3 - s_cluster) + (log sumexp(tail) - z_target)
// Pipeline:
//   k_convert_B : logits [1024][50257] f32 -> g_Bt [50257][1024] bf16 (K-major)
//   k_cluster   : cluster head (fp32), zero accumulators
//   k_bucket    : bucket tokens by cluster
//   k_convert_x : x rows (bucketed order) -> g_Ab [4096][1024] bf16
//   k_main_mma  : 128x128 CTA tile GEMM (BK=32, cp.async 3-stage) fused with
//                 sum-of-exp + target capture (no max pass: |z| < ~5)
//   k_final     : nll = rownll + log(sumexp) - tgt
// ---------------------------------------------------------------------------

#define MAX_TOK 4096
#define HID 1024
#define NCL 3
#define MAX_VOCAB 50257

__device__ int   g_order[MAX_TOK];
__device__ int   g_counts[NCL];
__device__ int   g_bases[NCL];
__device__ float g_rownll[MAX_TOK];
__device__ float g_sumexp[MAX_TOK];
__device__ float g_tgt[MAX_TOK];
__device__ __nv_bfloat16 g_Ab[(size_t)MAX_TOK * HID];        // 8 MB
__device__ __nv_bfloat16 g_Bt[(size_t)MAX_VOCAB * HID];      // ~103 MB

__device__ __forceinline__ int cluster_of(int yy) {
    return yy < 20000 ? 0 : (yy < 40000 ? 1 : 2);
}

// ---------------- PTX helpers (baseline PTX only, no 'a' features) ---------
__device__ __forceinline__ uint32_t smem_u32(const void* p) {
    uint32_t a;
    asm("{ .reg .u64 t; cvta.to.shared.u64 t, %1; cvt.u32.u64 %0, t; }"
        : "=r"(a) : "l"(p));
    return a;
}
__device__ __forceinline__ void cp16(uint32_t dst, const void* src) {
    size_t g = __cvta_generic_to_global(src);
    asm volatile("cp.async.cg.shared.global [%0], [%1], 16;"
                 :: "r"(dst), "l"(g) : "memory");
}
#define CP_COMMIT() asm volatile("cp.async.commit_group;" ::: "memory")

__device__ __forceinline__ void ldm_x4(uint32_t* r, uint32_t addr) {
    asm volatile("ldmatrix.sync.aligned.m8n8.x4.shared.b16 {%0,%1,%2,%3}, [%4];"
                 : "=r"(r[0]), "=r"(r[1]), "=r"(r[2]), "=r"(r[3]) : "r"(addr));
}
__device__ __forceinline__ void mma_bf16(float* d, const uint32_t* a,
                                         const uint32_t* b) {
    asm volatile(
        "mma.sync.aligned.m16n8k16.row.col.f32.bf16.bf16.f32 "
        "{%0,%1,%2,%3}, {%4,%5,%6,%7}, {%8,%9}, {%0,%1,%2,%3};"
        : "+f"(d[0]), "+f"(d[1]), "+f"(d[2]), "+f"(d[3])
        : "r"(a[0]), "r"(a[1]), "r"(a[2]), "r"(a[3]), "r"(b[0]), "r"(b[1]));
}

// ---------------------------------------------------------------------------
// K0: transpose+convert logits -> g_Bt [vocab][1024] bf16
// ---------------------------------------------------------------------------
__global__ void k_convert_B(const float* __restrict__ logits, int vocab) {
    __shared__ float tile[32][33];
    int nb = blockIdx.x * 32, kb = blockIdx.y * 32;
    int tx = threadIdx.x, ty = threadIdx.y;  // (32, 8)
#pragma unroll
    for (int j = 0; j < 32; j += 8) {
        int n = nb + tx;
        tile[ty + j][tx] = (n < vocab)
            ? logits[(size_t)(kb + ty + j) * vocab + n] : 0.f;
    }
    __syncthreads();
#pragma unroll
    for (int j = 0; j < 32; j += 8) {
        int n = nb + ty + j;
        if (n < vocab)
            g_Bt[(size_t)n * HID + kb + tx] = __float2bfloat16(tile[tx][ty + j]);
    }
}

// ---------------------------------------------------------------------------
// K1: cluster head (fp32) + zero accumulators
// ---------------------------------------------------------------------------
__global__ void k_cluster(const float* __restrict__ x,
                          const int* __restrict__ y,
                          const float* __restrict__ Wc, int n) {
    int warp = (blockIdx.x * blockDim.x + threadIdx.x) >> 5;
    int lane = threadIdx.x & 31;
    if (warp >= n) return;
    const float* xr = x + (size_t)warp * HID;
    float s0 = 0.f, s1 = 0.f, s2 = 0.f;
    for (int k = lane; k < HID; k += 32) {
        float xv = xr[k];
        s0 += xv * Wc[k];
        s1 += xv * Wc[HID + k];
        s2 += xv * Wc[2 * HID + k];
    }
#pragma unroll
    for (int m = 16; m; m >>= 1) {
        s0 += __shfl_xor_sync(0xffffffffu, s0, m);
        s1 += __shfl_xor_sync(0xffffffffu, s1, m);
        s2 += __shfl_xor_sync(0xffffffffu, s2, m);
    }
    if (lane == 0) {
        int cy = cluster_of(y[warp]);
        float mx = fmaxf(s0, fmaxf(s1, s2));
        float lse = logf(expf(s0 - mx) + expf(s1 - mx) + expf(s2 - mx)) + mx;
        float sc = (cy == 0) ? s0 : ((cy == 1) ? s1 : s2);
        g_rownll[warp] = lse - sc;
        g_sumexp[warp] = 0.f;
        g_tgt[warp] = 0.f;
    }
}

// ---------------------------------------------------------------------------
// K2: bucket tokens
// ---------------------------------------------------------------------------
__global__ void k_bucket(const int* __restrict__ y, int n) {
    __shared__ int cnt[NCL];
    __shared__ int base[NCL];
    int tid = threadIdx.x;
    if (tid < NCL) cnt[tid] = 0;
    __syncthreads();
    for (int t = tid; t < n; t += blockDim.x)
        atomicAdd(&cnt[cluster_of(y[t])], 1);
    __syncthreads();
    if (tid == 0) {
        g_counts[0] = cnt[0]; g_counts[1] = cnt[1]; g_counts[2] = cnt[2];
        g_bases[0] = 0; g_bases[1] = cnt[0]; g_bases[2] = cnt[0] + cnt[1];
        base[0] = 0; base[1] = cnt[0]; base[2] = cnt[0] + cnt[1];
        cnt[0] = cnt[1] = cnt[2] = 0;
    }
    __syncthreads();
    for (int t = tid; t < n; t += blockDim.x) {
        int c = cluster_of(y[t]);
        int idx = atomicAdd(&cnt[c], 1);
        g_order[base[c] + idx] = t;
    }
}

// ---------------------------------------------------------------------------
// K3: gather+convert x rows (bucketed order) -> g_Ab bf16
// ---------------------------------------------------------------------------
__global__ void k_convert_x(const float* __restrict__ x) {
    int row = blockIdx.x;
    int t = g_order[row];
    const float4* src = (const float4*)(x + (size_t)t * HID);
    __nv_bfloat162* dst = (__nv_bfloat162*)(g_Ab + (size_t)row * HID);
#pragma unroll
    for (int j = threadIdx.x; j < HID / 4; j += 128) {
        float4 v = src[j];
        dst[j * 2 + 0] = __floats2bfloat162_rn(v.x, v.y);
        dst[j * 2 + 1] = __floats2bfloat162_rn(v.z, v.w);
    }
}

// ---------------------------------------------------------------------------
// K4: main GEMM. CTA tile 128(M)x128(N), BK=32, 256 threads (2x4 warps),
// each warp 64x32 via m16n8k16. 3-stage cp.async pipeline.
// ---------------------------------------------------------------------------
#define BK 32
#define PAD 40                         // smem row stride in bf16 (80 B)
#define ABYTES (128 * PAD * 2)         // 10240
#define STAGE (2 * ABYTES)             // 20480
#define SMEM_DYN (3 * STAGE)           // 61440

struct TA { int abase, row0, count, l, col0, vocab; };

__device__ __forceinline__ void load_tile(uint32_t sb, int it, int stage,
                                          int tid, const TA& ta) {
    const int k0 = it * BK;
    const uint32_t As = sb + stage * STAGE;
    const uint32_t Bs = As + ABYTES;
    // A: 128 rows x 32 k bf16 = 512 x 16B chunks
#pragma unroll
    for (int j = 0; j < 2; j++) {
        int q = tid + j * 256;
        int row = q >> 2, cc = q & 3;
        int rl = ta.row0 + row;
        int ridx = ta.abase + (rl < ta.count ? rl : ta.count - 1);
        cp16(As + row * (PAD * 2) + cc * 16,
             g_Ab + (size_t)ridx * HID + k0 + cc * 8);
    }
    // B: 128 cols x 32 k
#pragma unroll
    for (int j = 0; j < 2; j++) {
        int q = tid + j * 256;
        int row = q >> 2, cc = q & 3;
        int col = ta.l + ta.col0 + row;
        if (col >= ta.vocab) col = ta.vocab - 1;
        cp16(Bs + row * (PAD * 2) + cc * 16,
             g_Bt + (size_t)col * HID + k0 + cc * 8);
    }
    CP_COMMIT();
}

__global__ __launch_bounds__(256)
void k_main_mma(const int* __restrict__ y, int vocab) {
    extern __shared__ char dsm[];
    __shared__ int stok[128];
    __shared__ int sy[128];

    const int c = blockIdx.z;
    const int l = (c == 0) ? 0 : ((c == 1) ? 20000 : 40000);
    const int r = (c == 0) ? 20000 : ((c == 1) ? 40000 : vocab);
    const int ncols = r - l;
    const int col0 = blockIdx.x * 128;
    if (col0 >= ncols) return;
    const int count = g_counts[c];
    const int row0 = blockIdx.y * 128;
    if (row0 >= count) return;
    const int abase = g_bases[c];

    const int tid = threadIdx.x;
    const int wid = tid >> 5;
    const int lane = tid & 31;
    const int warp_m = wid & 1;      // 0..1
    const int warp_n = wid >> 1;     // 0..3

    const uint32_t sb = smem_u32(dsm);

    if (tid < 128) {
        int rl = row0 + tid;
        int ridx = abase + (rl < count ? rl : count - 1);
        int t = g_order[ridx];
        stok[tid] = t;
        sy[tid] = y[t] - l;
    }
    __syncthreads();

    TA ta{abase, row0, count, l, col0, vocab};

    float acc[4][4][4];
#pragma unroll
    for (int i = 0; i < 4; i++)
#pragma unroll
        for (int j = 0; j < 4; j++)
#pragma unroll
            for (int q = 0; q < 4; q++) acc[i][j][q] = 0.f;

    load_tile(sb, 0, 0, tid, ta);
    load_tile(sb, 1, 1, tid, ta);

    const int KIT = HID / BK;  // 32
    for (int it = 0; it < KIT; it++) {
        if (it < KIT - 1)
            asm volatile("cp.async.wait_group 1;" ::: "memory");
        else
            asm volatile("cp.async.wait_group 0;" ::: "memory");
        __syncthreads();
        if (it + 2 < KIT) load_tile(sb, it + 2, (it + 2) % 3, tid, ta);

        const uint32_t As = sb + (it % 3) * STAGE;
        const uint32_t Bs = As + ABYTES;
#pragma unroll
        for (int kk = 0; kk < 2; kk++) {
            uint32_t af[4][4], bf[4][2];
#pragma unroll
            for (int mf = 0; mf < 4; mf++) {
                uint32_t addr = As +
                    ((warp_m * 64 + mf * 16 + (lane & 15)) * PAD +
                     kk * 16 + (lane >> 4) * 8) * 2;
                ldm_x4(af[mf], addr);
            }
#pragma unroll
            for (int np = 0; np < 2; np++) {
                uint32_t rr[4];
                uint32_t addr = Bs +
                    ((warp_n * 32 + np * 16 + ((lane >> 4) << 3) + (lane & 7)) * PAD +
                     kk * 16 + ((lane >> 3) & 1) * 8) * 2;
                ldm_x4(rr, addr);
                bf[np * 2 + 0][0] = rr[0]; bf[np * 2 + 0][1] = rr[1];
                bf[np * 2 + 1][0] = rr[2]; bf[np * 2 + 1][1] = rr[3];
            }
#pragma unroll
            for (int mf = 0; mf < 4; mf++)
#pragma unroll
                for (int nf = 0; nf < 4; nf++)
                    mma_bf16(acc[mf][nf], af[mf], bf[nf]);
        }
    }

    // ---- epilogue: per-row sumexp + target capture ----
    const int qid = lane >> 2;    // row within 8
    const int qlane = lane & 3;   // column quad
#pragma unroll
    for (int mf = 0; mf < 4; mf++) {
#pragma unroll
        for (int h = 0; h < 2; h++) {
            int rl = warp_m * 64 + mf * 16 + qid + h * 8;
            int rg = row0 + rl;
            bool valid = rg < count;
            int t = stok[rl];
            int ytc = sy[rl];
            float s = 0.f, tgtv = 0.f;
            bool hit = false;
#pragma unroll
            for (int nf = 0; nf < 4; nf++) {
                float v0 = acc[mf][nf][h * 2 + 0];
                float v1 = acc[mf][nf][h * 2 + 1];
                int cl = col0 + warp_n * 32 + nf * 8 + qlane * 2;
                if (cl < ncols) {
                    s += __expf(v0);
                    if (cl == ytc) { tgtv = v0; hit = true; }
                }
                if (cl + 1 < ncols) {
                    s += __expf(v1);
                    if (cl + 1 == ytc) { tgtv = v1; hit = true; }
                }
            }
            s += __shfl_xor_sync(0xffffffffu, s, 1);
            s += __shfl_xor_sync(0xffffffffu, s, 2);
            if (valid) {
                if (hit) g_tgt[t] = tgtv;
                if (qlane == 0) atomicAdd(&g_sumexp[t], s);
            }
        }
    }
}

// ---------------------------------------------------------------------------
// K5: finalize
// ---------------------------------------------------------------------------
__global__ void k_final(float* __restrict__ out, int n) {
    int t = blockIdx.x * blockDim.x + threadIdx.x;
    if (t >= n) return;
    out[t] = g_rownll[t] + logf(g_sumexp[t]) - g_tgt[t];
}

// ---------------------------------------------------------------------------
extern "C" void kernel_launch(void* const* d_in, const int* in_sizes, int n_in,
                              void* d_out, int out_size) {
    const float* x = (const float*)d_in[0];
    const int* y = (const int*)d_in[1];
    const float* Wc = (const float*)d_in[2];
    const float* logits = (const float*)d_in[3];
    float* out = (float*)d_out;

    int n = in_sizes[1];               // 4096
    int hidden = in_sizes[0] / n;      // 1024
    int vocab = in_sizes[3] / hidden;  // 50257

    cudaFuncSetAttribute(k_main_mma,
                         cudaFuncAttributeMaxDynamicSharedMemorySize, SMEM_DYN);

    // B convert/transpose (independent, biggest — launch first)
    k_convert_B<<<dim3((vocab + 31) / 32, hidden / 32), dim3(32, 8)>>>(logits, vocab);
    // cluster head
    k_cluster<<<(n + 7) / 8, 256>>>(x, y, Wc, n);
    // bucket
    k_bucket<<<1, 1024>>>(y, n);
    // A gather+convert (depends on bucket)
    k_convert_x<<<n, 128>>>(x);
    // main tensor kernel
    int maxcols = 20000;
    dim3 grid((maxcols + 127) / 128, (n + 127) / 128, 3);
    k_main_mma<<<grid, 256, SMEM_DYN>>>(y, vocab);
    // finalize
    k_final<<<(n + 255) / 256, 256>>>(out, n);
}

// round 6
// speedup vs baseline: 5.6240x; 1.4453x over previous
#include <cuda_runtime.h>
#include <cuda_bf16.h>
#include <cstdint>

// ---------------------------------------------------------------------------
// FactorizedSoftmaxV2 via mma.sync bf16 (HMMA; tcgen05 PTX rejected at the
// harness's compute_103 virtual arch).
//   nll[t] = (lse3 - s_cluster) + (log sumexp(tail) - z_target)
// R6: CTA tile 128x256 (warp tile 64x64), coalesced convert_B writes.
// ---------------------------------------------------------------------------

#define MAX_TOK 4096
#define HID 1024
#define NCL 3
#define MAX_VOCAB 50257

__device__ int   g_order[MAX_TOK];
__device__ int   g_counts[NCL];
__device__ int   g_bases[NCL];
__device__ float g_rownll[MAX_TOK];
__device__ float g_sumexp[MAX_TOK];
__device__ float g_tgt[MAX_TOK];
__device__ __nv_bfloat16 g_Ab[(size_t)MAX_TOK * HID];        // 8 MB
__device__ __nv_bfloat16 g_Bt[(size_t)MAX_VOCAB * HID];      // ~103 MB

__device__ __forceinline__ int cluster_of(int yy) {
    return yy < 20000 ? 0 : (yy < 40000 ? 1 : 2);
}

// ---------------- PTX helpers (baseline PTX only) ----------------
__device__ __forceinline__ uint32_t smem_u32(const void* p) {
    uint32_t a;
    asm("{ .reg .u64 t; cvta.to.shared.u64 t, %1; cvt.u32.u64 %0, t; }"
        : "=r"(a) : "l"(p));
    return a;
}
__device__ __forceinline__ void cp16(uint32_t dst, const void* src) {
    size_t g = __cvta_generic_to_global(src);
    asm volatile("cp.async.cg.shared.global [%0], [%1], 16;"
                 :: "r"(dst), "l"(g) : "memory");
}
#define CP_COMMIT() asm volatile("cp.async.commit_group;" ::: "memory")

__device__ __forceinline__ void ldm_x4(uint32_t* r, uint32_t addr) {
    asm volatile("ldmatrix.sync.aligned.m8n8.x4.shared.b16 {%0,%1,%2,%3}, [%4];"
                 : "=r"(r[0]), "=r"(r[1]), "=r"(r[2]), "=r"(r[3]) : "r"(addr));
}
__device__ __forceinline__ void mma_bf16(float* d, const uint32_t* a,
                                         const uint32_t* b) {
    asm volatile(
        "mma.sync.aligned.m16n8k16.row.col.f32.bf16.bf16.f32 "
        "{%0,%1,%2,%3}, {%4,%5,%6,%7}, {%8,%9}, {%0,%1,%2,%3};"
        : "+f"(d[0]), "+f"(d[1]), "+f"(d[2]), "+f"(d[3])
        : "r"(a[0]), "r"(a[1]), "r"(a[2]), "r"(a[3]), "r"(b[0]), "r"(b[1]));
}

// ---------------------------------------------------------------------------
// K0: transpose+convert logits -> g_Bt [vocab][1024] bf16.
// Block: 256 threads, tile 64(k) x 32(n). Reads coalesced 128B rows;
// writes: 8 threads per vocab row, uint4 (16B) each -> full 128B sectors.
// ---------------------------------------------------------------------------
__global__ void k_convert_B(const float* __restrict__ logits, int vocab) {
    __shared__ float tile[64][33];
    const int nb = blockIdx.x * 32;
    const int kb = blockIdx.y * 64;
    const int tid = threadIdx.x;
    // load 64 k-rows x 32 n
#pragma unroll
    for (int j = 0; j < 8; j++) {
        int idx = tid + j * 256;
        int k = idx >> 5, n = idx & 31;
        tile[k][n] = (nb + n < vocab)
            ? logits[(size_t)(kb + k) * vocab + nb + n] : 0.f;
    }
    __syncthreads();
    // write: thread -> (n_loc = tid>>3, kq = tid&7): 8 bf16 = 16B
    const int n_loc = tid >> 3;
    const int kq = (tid & 7) * 8;
    const int n = nb + n_loc;
    if (n < vocab) {
        uint32_t w[4];
#pragma unroll
        for (int i = 0; i < 4; i++) {
            __nv_bfloat162 p = __floats2bfloat162_rn(tile[kq + i * 2][n_loc],
                                                     tile[kq + i * 2 + 1][n_loc]);
            w[i] = *(uint32_t*)&p;
        }
        *(uint4*)(g_Bt + (size_t)n * HID + kb + kq) = *(uint4*)w;
    }
}

// ---------------------------------------------------------------------------
// K1: cluster head (fp32) + zero accumulators
// ---------------------------------------------------------------------------
__global__ void k_cluster(const float* __restrict__ x,
                          const int* __restrict__ y,
                          const float* __restrict__ Wc, int n) {
    int warp = (blockIdx.x * blockDim.x + threadIdx.x) >> 5;
    int lane = threadIdx.x & 31;
    if (warp >= n) return;
    const float* xr = x + (size_t)warp * HID;
    float s0 = 0.f, s1 = 0.f, s2 = 0.f;
    for (int k = lane; k < HID; k += 32) {
        float xv = xr[k];
        s0 += xv * Wc[k];
        s1 += xv * Wc[HID + k];
        s2 += xv * Wc[2 * HID + k];
    }
#pragma unroll
    for (int m = 16; m; m >>= 1) {
        s0 += __shfl_xor_sync(0xffffffffu, s0, m);
        s1 += __shfl_xor_sync(0xffffffffu, s1, m);
        s2 += __shfl_xor_sync(0xffffffffu, s2, m);
    }
    if (lane == 0) {
        int cy = cluster_of(y[warp]);
        float mx = fmaxf(s0, fmaxf(s1, s2));
        float lse = logf(expf(s0 - mx) + expf(s1 - mx) + expf(s2 - mx)) + mx;
        float sc = (cy == 0) ? s0 : ((cy == 1) ? s1 : s2);
        g_rownll[warp] = lse - sc;
        g_sumexp[warp] = 0.f;
        g_tgt[warp] = 0.f;
    }
}

// ---------------------------------------------------------------------------
// K2: bucket tokens
// ---------------------------------------------------------------------------
__global__ void k_bucket(const int* __restrict__ y, int n) {
    __shared__ int cnt[NCL];
    __shared__ int base[NCL];
    int tid = threadIdx.x;
    if (tid < NCL) cnt[tid] = 0;
    __syncthreads();
    for (int t = tid; t < n; t += blockDim.x)
        atomicAdd(&cnt[cluster_of(y[t])], 1);
    __syncthreads();
    if (tid == 0) {
        g_counts[0] = cnt[0]; g_counts[1] = cnt[1]; g_counts[2] = cnt[2];
        g_bases[0] = 0; g_bases[1] = cnt[0]; g_bases[2] = cnt[0] + cnt[1];
        base[0] = 0; base[1] = cnt[0]; base[2] = cnt[0] + cnt[1];
        cnt[0] = cnt[1] = cnt[2] = 0;
    }
    __syncthreads();
    for (int t = tid; t < n; t += blockDim.x) {
        int c = cluster_of(y[t]);
        int idx = atomicAdd(&cnt[c], 1);
        g_order[base[c] + idx] = t;
    }
}

// ---------------------------------------------------------------------------
// K3: gather+convert x rows (bucketed order) -> g_Ab bf16
// ---------------------------------------------------------------------------
__global__ void k_convert_x(const float* __restrict__ x) {
    int row = blockIdx.x;
    int t = g_order[row];
    const float4* src = (const float4*)(x + (size_t)t * HID);
    __nv_bfloat162* dst = (__nv_bfloat162*)(g_Ab + (size_t)row * HID);
#pragma unroll
    for (int j = threadIdx.x; j < HID / 4; j += 128) {
        float4 v = src[j];
        dst[j * 2 + 0] = __floats2bfloat162_rn(v.x, v.y);
        dst[j * 2 + 1] = __floats2bfloat162_rn(v.z, v.w);
    }
}

// ---------------------------------------------------------------------------
// K4: main GEMM. CTA tile 128(M)x256(N), BK=32, 256 threads (2x4 warps),
// each warp 64x64 via m16n8k16. 3-stage cp.async pipeline.
// ---------------------------------------------------------------------------
#define BK 32
#define PAD 40                          // smem row stride in bf16 (80 B)
#define ABYTES (128 * PAD * 2)          // 10240
#define BBYTES (256 * PAD * 2)          // 20480
#define STAGE (ABYTES + BBYTES)         // 30720
#define SMEM_DYN (3 * STAGE)            // 92160

struct TA { int abase, row0, count, l, col0, vocab; };

__device__ __forceinline__ void load_tile(uint32_t sb, int it, int stage,
                                          int tid, const TA& ta) {
    const int k0 = it * BK;
    const uint32_t As = sb + stage * STAGE;
    const uint32_t Bs = As + ABYTES;
    // A: 128 rows x 32 k bf16 = 512 x 16B chunks
#pragma unroll
    for (int j = 0; j < 2; j++) {
        int q = tid + j * 256;
        int row = q >> 2, cc = q & 3;
        int rl = ta.row0 + row;
        int ridx = ta.abase + (rl < ta.count ? rl : ta.count - 1);
        cp16(As + row * (PAD * 2) + cc * 16,
             g_Ab + (size_t)ridx * HID + k0 + cc * 8);
    }
    // B: 256 cols x 32 k
#pragma unroll
    for (int j = 0; j < 4; j++) {
        int q = tid + j * 256;
        int row = q >> 2, cc = q & 3;
        int col = ta.l + ta.col0 + row;
        if (col >= ta.vocab) col = ta.vocab - 1;
        cp16(Bs + row * (PAD * 2) + cc * 16,
             g_Bt + (size_t)col * HID + k0 + cc * 8);
    }
    CP_COMMIT();
}

__global__ __launch_bounds__(256, 1)
void k_main_mma(const int* __restrict__ y, int vocab) {
    extern __shared__ char dsm[];
    __shared__ int stok[128];
    __shared__ int sy[128];

    const int c = blockIdx.z;
    const int l = (c == 0) ? 0 : ((c == 1) ? 20000 : 40000);
    const int r = (c == 0) ? 20000 : ((c == 1) ? 40000 : vocab);
    const int ncols = r - l;
    const int col0 = blockIdx.x * 256;
    if (col0 >= ncols) return;
    const int count = g_counts[c];
    const int row0 = blockIdx.y * 128;
    if (row0 >= count) return;
    const int abase = g_bases[c];

    const int tid = threadIdx.x;
    const int wid = tid >> 5;
    const int lane = tid & 31;
    const int warp_m = wid & 1;      // 0..1  (64-row slab)
    const int warp_n = wid >> 1;     // 0..3  (64-col slab)

    const uint32_t sb = smem_u32(dsm);

    if (tid < 128) {
        int rl = row0 + tid;
        int ridx = abase + (rl < count ? rl : count - 1);
        int t = g_order[ridx];
        stok[tid] = t;
        sy[tid] = y[t] - l;
    }
    __syncthreads();

    TA ta{abase, row0, count, l, col0, vocab};

    float acc[4][8][4];
#pragma unroll
    for (int i = 0; i < 4; i++)
#pragma unroll
        for (int j = 0; j < 8; j++)
#pragma unroll
            for (int q = 0; q < 4; q++) acc[i][j][q] = 0.f;

    load_tile(sb, 0, 0, tid, ta);
    load_tile(sb, 1, 1, tid, ta);

    const int KIT = HID / BK;  // 32
    for (int it = 0; it < KIT; it++) {
        if (it < KIT - 1)
            asm volatile("cp.async.wait_group 1;" ::: "memory");
        else
            asm volatile("cp.async.wait_group 0;" ::: "memory");
        __syncthreads();
        if (it + 2 < KIT) load_tile(sb, it + 2, (it + 2) % 3, tid, ta);

        const uint32_t As = sb + (it % 3) * STAGE;
        const uint32_t Bs = As + ABYTES;
#pragma unroll
        for (int kk = 0; kk < 2; kk++) {
            uint32_t af[4][4], bf[8][2];
#pragma unroll
            for (int mf = 0; mf < 4; mf++) {
                uint32_t addr = As +
                    ((warp_m * 64 + mf * 16 + (lane & 15)) * PAD +
                     kk * 16 + (lane >> 4) * 8) * 2;
                ldm_x4(af[mf], addr);
            }
#pragma unroll
            for (int np = 0; np < 4; np++) {
                uint32_t rr[4];
                uint32_t addr = Bs +
                    ((warp_n * 64 + np * 16 + ((lane >> 4) << 3) + (lane & 7)) * PAD +
                     kk * 16 + ((lane >> 3) & 1) * 8) * 2;
                ldm_x4(rr, addr);
                bf[np * 2 + 0][0] = rr[0]; bf[np * 2 + 0][1] = rr[1];
                bf[np * 2 + 1][0] = rr[2]; bf[np * 2 + 1][1] = rr[3];
            }
#pragma unroll
            for (int mf = 0; mf < 4; mf++)
#pragma unroll
                for (int nf = 0; nf < 8; nf++)
                    mma_bf16(acc[mf][nf], af[mf], bf[nf]);
        }
    }

    // ---- epilogue: per-row sumexp + target capture ----
    const int qid = lane >> 2;    // row within 8
    const int qlane = lane & 3;   // column quad
#pragma unroll
    for (int mf = 0; mf < 4; mf++) {
#pragma unroll
        for (int h = 0; h < 2; h++) {
            int rl = warp_m * 64 + mf * 16 + qid + h * 8;
            int rg = row0 + rl;
            bool valid = rg < count;
            int t = stok[rl];
            int ytc = sy[rl];
            float s = 0.f, tgtv = 0.f;
            bool hit = false;
#pragma unroll
            for (int nf = 0; nf < 8; nf++) {
                float v0 = acc[mf][nf][h * 2 + 0];
                float v1 = acc[mf][nf][h * 2 + 1];
                int cl = col0 + warp_n * 64 + nf * 8 + qlane * 2;
                if (cl < ncols) {
                    s += __expf(v0);
                    if (cl == ytc) { tgtv = v0; hit = true; }
                }
                if (cl + 1 < ncols) {
                    s += __expf(v1);
                    if (cl + 1 == ytc) { tgtv = v1; hit = true; }
                }
            }
            s += __shfl_xor_sync(0xffffffffu, s, 1);
            s += __shfl_xor_sync(0xffffffffu, s, 2);
            if (valid) {
                if (hit) g_tgt[t] = tgtv;
                if (qlane == 0) atomicAdd(&g_sumexp[t], s);
            }
        }
    }
}

// ---------------------------------------------------------------------------
// K5: finalize
// ---------------------------------------------------------------------------
__global__ void k_final(float* __restrict__ out, int n) {
    int t = blockIdx.x * blockDim.x + threadIdx.x;
    if (t >= n) return;
    out[t] = g_rownll[t] + logf(g_sumexp[t]) - g_tgt[t];
}

// ---------------------------------------------------------------------------
extern "C" void kernel_launch(void* const* d_in, const int* in_sizes, int n_in,
                              void* d_out, int out_size) {
    const float* x = (const float*)d_in[0];
    const int* y = (const int*)d_in[1];
    const float* Wc = (const float*)d_in[2];
    const float* logits = (const float*)d_in[3];
    float* out = (float*)d_out;

    int n = in_sizes[1];               // 4096
    int hidden = in_sizes[0] / n;      // 1024
    int vocab = in_sizes[3] / hidden;  // 50257

    cudaFuncSetAttribute(k_main_mma,
                         cudaFuncAttributeMaxDynamicSharedMemorySize, SMEM_DYN);

    // B convert/transpose (independent, biggest — launch first)
    k_convert_B<<<dim3((vocab + 31) / 32, hidden / 64), 256>>>(logits, vocab);
    // cluster head
    k_cluster<<<(n + 7) / 8, 256>>>(x, y, Wc, n);
    // bucket
    k_bucket<<<1, 1024>>>(y, n);
    // A gather+convert (depends on bucket)
    k_convert_x<<<n, 128>>>(x);
    // main tensor kernel
    int maxcols = 20000;
    dim3 grid((maxcols + 255) / 256, (n + 127) / 128, 3);
    k_main_mma<<<grid, 256, SMEM_DYN>>>(y, vocab);
    // finalize
    k_final<<<(n + 255) / 256, 256>>>(out, n);
}

// round 8
// speedup vs baseline: 6.4567x; 1.1481x over previous
#include <cuda_runtime.h>
#include <cuda_bf16.h>
#include <cuda_fp8.h>
#include <cstdint>

// ---------------------------------------------------------------------------
// FactorizedSoftmaxV2, R8: fp8 (e4m3) mma.sync GEMM for the log-sum-exp
// (random quantization errors average out across 20000 columns), plus an
// exact fp32 dot-product kernel for the target logit.
//   nll[t] = (lse3 - s_cluster) + (log sumexp(z_fp8) - z_tgt_fp32)
// Launch order (ncu profiles launch index 3 => k_main):
//   0 k_convert_B (logits*64 -> e4m3 [vocab][1024], also zeros g_counts)
//   1 k_cluster_bucket (cluster head + atomic bucketing)
//   2 k_convert_x (x -> e4m3, bucketed rows)
//   3 k_main_mma (128x256 CTA tile, m16n8k32 e4m3)
//   4 k_tgt (exact fp32 target logits)
//   5 k_final
// ---------------------------------------------------------------------------

#define MAX_TOK 4096
#define HID 1024
#define NCL 3
#define MAX_VOCAB 50257
#define BSCALE 64.0f
#define INV_BSCALE 0.015625f

__device__ int    g_order[NCL * MAX_TOK];
__device__ int    g_counts[NCL];
__device__ float  g_rownll[MAX_TOK];
__device__ float  g_sumexp[MAX_TOK];
__device__ float  g_tgt[MAX_TOK];
__device__ uint8_t g_A8[(size_t)NCL * MAX_TOK * HID];     // 12 MB (e4m3)
__device__ uint8_t g_B8[(size_t)MAX_VOCAB * HID];         // ~51 MB (e4m3)

__device__ __forceinline__ int cluster_of(int yy) {
    return yy < 20000 ? 0 : (yy < 40000 ? 1 : 2);
}

// ---------------- PTX helpers (baseline PTX only) ----------------
__device__ __forceinline__ uint32_t smem_u32(const void* p) {
    uint32_t a;
    asm("{ .reg .u64 t; cvta.to.shared.u64 t, %1; cvt.u32.u64 %0, t; }"
        : "=r"(a) : "l"(p));
    return a;
}
__device__ __forceinline__ void cp16(uint32_t dst, const void* src) {
    size_t g = __cvta_generic_to_global(src);
    asm volatile("cp.async.cg.shared.global [%0], [%1], 16;"
                 :: "r"(dst), "l"(g) : "memory");
}
#define CP_COMMIT() asm volatile("cp.async.commit_group;" ::: "memory")

__device__ __forceinline__ void ldm_x4(uint32_t* r, uint32_t addr) {
    asm volatile("ldmatrix.sync.aligned.m8n8.x4.shared.b16 {%0,%1,%2,%3}, [%4];"
                 : "=r"(r[0]), "=r"(r[1]), "=r"(r[2]), "=r"(r[3]) : "r"(addr));
}
__device__ __forceinline__ void mma_fp8(float* d, const uint32_t* a,
                                        const uint32_t* b) {
    asm volatile(
        "mma.sync.aligned.m16n8k32.row.col.f32.e4m3.e4m3.f32 "
        "{%0,%1,%2,%3}, {%4,%5,%6,%7}, {%8,%9}, {%0,%1,%2,%3};"
        : "+f"(d[0]), "+f"(d[1]), "+f"(d[2]), "+f"(d[3])
        : "r"(a[0]), "r"(a[1]), "r"(a[2]), "r"(a[3]), "r"(b[0]), "r"(b[1]));
}

__device__ __forceinline__ uint16_t f2_to_fp8x2(float a, float b) {
    return (uint16_t)__nv_cvt_float2_to_fp8x2(make_float2(a, b),
                                              __NV_SATFINITE, __NV_E4M3);
}

// ---------------------------------------------------------------------------
// L0: logits [1024][vocab] f32 -> g_B8 [vocab][1024] e4m3 (scaled by 64).
// Also zeroes g_counts (runs before k_cluster_bucket in stream order).
// ---------------------------------------------------------------------------
__global__ void k_convert_B(const float* __restrict__ logits, int vocab) {
    __shared__ float tile[64][33];
    if (blockIdx.x == 0 && blockIdx.y == 0 && threadIdx.x < NCL)
        g_counts[threadIdx.x] = 0;
    const int nb = blockIdx.x * 32;
    const int kb = blockIdx.y * 64;
    const int tid = threadIdx.x;
#pragma unroll
    for (int j = 0; j < 8; j++) {
        int idx = tid + j * 256;
        int k = idx >> 5, n = idx & 31;
        tile[k][n] = (nb + n < vocab)
            ? logits[(size_t)(kb + k) * vocab + nb + n] : 0.f;
    }
    __syncthreads();
    const int n_loc = tid >> 3;          // 0..31
    const int kq = (tid & 7) * 8;        // 0..56
    const int n = nb + n_loc;
    if (n < vocab) {
        uint16_t w[4];
#pragma unroll
        for (int i = 0; i < 4; i++)
            w[i] = f2_to_fp8x2(tile[kq + i * 2][n_loc] * BSCALE,
                               tile[kq + i * 2 + 1][n_loc] * BSCALE);
        *(uint2*)(g_B8 + (size_t)n * HID + kb + kq) = *(uint2*)w;
    }
}

// ---------------------------------------------------------------------------
// L1: cluster head (fp32) + atomic bucketing + zero sumexp
// ---------------------------------------------------------------------------
__global__ void k_cluster_bucket(const float* __restrict__ x,
                                 const int* __restrict__ y,
                                 const float* __restrict__ Wc, int n) {
    int warp = (blockIdx.x * blockDim.x + threadIdx.x) >> 5;
    int lane = threadIdx.x & 31;
    if (warp >= n) return;
    const float* xr = x + (size_t)warp * HID;
    float s0 = 0.f, s1 = 0.f, s2 = 0.f;
    for (int k = lane; k < HID; k += 32) {
        float xv = xr[k];
        s0 += xv * Wc[k];
        s1 += xv * Wc[HID + k];
        s2 += xv * Wc[2 * HID + k];
    }
#pragma unroll
    for (int m = 16; m; m >>= 1) {
        s0 += __shfl_xor_sync(0xffffffffu, s0, m);
        s1 += __shfl_xor_sync(0xffffffffu, s1, m);
        s2 += __shfl_xor_sync(0xffffffffu, s2, m);
    }
    if (lane == 0) {
        int cy = cluster_of(y[warp]);
        float mx = fmaxf(s0, fmaxf(s1, s2));
        float lse = logf(expf(s0 - mx) + expf(s1 - mx) + expf(s2 - mx)) + mx;
        float sc = (cy == 0) ? s0 : ((cy == 1) ? s1 : s2);
        g_rownll[warp] = lse - sc;
        g_sumexp[warp] = 0.f;
        int slot = atomicAdd(&g_counts[cy], 1);
        g_order[cy * MAX_TOK + slot] = warp;
    }
}

// ---------------------------------------------------------------------------
// L2: gather+convert x rows -> g_A8 e4m3 (bucketed). grid (MAX_TOK, 3).
// ---------------------------------------------------------------------------
__global__ void k_convert_x(const float* __restrict__ x) {
    const int c = blockIdx.y;
    const int r = blockIdx.x;
    if (r >= g_counts[c]) return;
    const int t = g_order[c * MAX_TOK + r];
    const float4* src = (const float4*)(x + (size_t)t * HID);
    uint8_t* dst = g_A8 + (size_t)(c * MAX_TOK + r) * HID;
    // thread: 8 consecutive floats -> 8 e4m3 bytes
    const int j = threadIdx.x;           // 0..127
    float4 v0 = src[j * 2];
    float4 v1 = src[j * 2 + 1];
    uint16_t w[4];
    w[0] = f2_to_fp8x2(v0.x, v0.y);
    w[1] = f2_to_fp8x2(v0.z, v0.w);
    w[2] = f2_to_fp8x2(v1.x, v1.y);
    w[3] = f2_to_fp8x2(v1.z, v1.w);
    *(uint2*)(dst + j * 8) = *(uint2*)w;
}

// ---------------------------------------------------------------------------
// L3: main GEMM. CTA 128(M)x256(N), BK=64 (fp8), 256 threads (2x4 warps),
// warp tile 64x64 via m16n8k32.e4m3. 3-stage cp.async pipeline.
// Row layout: 80 B (64 data + 16 pad) -> conflict-free ldmatrix.
// ---------------------------------------------------------------------------
#define BK 64
#define ROWB 80
#define ABYTES (128 * ROWB)             // 10240
#define BBYTES (256 * ROWB)             // 20480
#define STAGE (ABYTES + BBYTES)         // 30720
#define SMEM_DYN (3 * STAGE)            // 92160

struct TA { int abase, row0, count, l, col0, vocab; };

__device__ __forceinline__ void load_tile(uint32_t sb, int it, int stage,
                                          int tid, const TA& ta) {
    const int k0 = it * BK;             // byte == elem for fp8
    const uint32_t As = sb + stage * STAGE;
    const uint32_t Bs = As + ABYTES;
    // A: 128 rows x 64 B = 512 x 16B chunks
#pragma unroll
    for (int j = 0; j < 2; j++) {
        int q = tid + j * 256;
        int row = q >> 2, cc = q & 3;
        int rl = ta.row0 + row;
        int ridx = ta.abase + (rl < ta.count ? rl : ta.count - 1);
        cp16(As + row * ROWB + cc * 16,
             g_A8 + (size_t)ridx * HID + k0 + cc * 16);
    }
    // B: 256 rows x 64 B = 1024 x 16B chunks
#pragma unroll
    for (int j = 0; j < 4; j++) {
        int q = tid + j * 256;
        int row = q >> 2, cc = q & 3;
        int col = ta.l + ta.col0 + row;
        if (col >= ta.vocab) col = ta.vocab - 1;
        cp16(Bs + row * ROWB + cc * 16,
             g_B8 + (size_t)col * HID + k0 + cc * 16);
    }
    CP_COMMIT();
}

__global__ __launch_bounds__(256, 1)
void k_main_mma(int vocab) {
    extern __shared__ char dsm[];
    __shared__ int stok[128];

    const int c = blockIdx.z;
    const int l = (c == 0) ? 0 : ((c == 1) ? 20000 : 40000);
    const int r = (c == 0) ? 20000 : ((c == 1) ? 40000 : vocab);
    const int ncols = r - l;
    const int col0 = blockIdx.x * 256;
    if (col0 >= ncols) return;
    const int count = g_counts[c];
    const int row0 = blockIdx.y * 128;
    if (row0 >= count) return;
    const int abase = c * MAX_TOK;

    const int tid = threadIdx.x;
    const int lane = tid & 31;
    const int wid = tid >> 5;
    const int warp_m = wid & 1;
    const int warp_n = wid >> 1;

    const uint32_t sb = smem_u32(dsm);

    if (tid < 128) {
        int rl = row0 + tid;
        stok[tid] = g_order[abase + (rl < count ? rl : count - 1)];
    }
    __syncthreads();

    TA ta{abase, row0, count, l, col0, vocab};

    float acc[4][8][4];
#pragma unroll
    for (int i = 0; i < 4; i++)
#pragma unroll
        for (int j = 0; j < 8; j++)
#pragma unroll
            for (int q = 0; q < 4; q++) acc[i][j][q] = 0.f;

    load_tile(sb, 0, 0, tid, ta);
    load_tile(sb, 1, 1, tid, ta);

    const int KIT = HID / BK;  // 16
    for (int it = 0; it < KIT; it++) {
        if (it < KIT - 1)
            asm volatile("cp.async.wait_group 1;" ::: "memory");
        else
            asm volatile("cp.async.wait_group 0;" ::: "memory");
        __syncthreads();
        if (it + 2 < KIT) load_tile(sb, it + 2, (it + 2) % 3, tid, ta);

        const uint32_t As = sb + (it % 3) * STAGE;
        const uint32_t Bs = As + ABYTES;
#pragma unroll
        for (int kk = 0; kk < 2; kk++) {    // 32 fp8 k-elems each
            uint32_t af[4][4], bf[8][2];
#pragma unroll
            for (int mf = 0; mf < 4; mf++) {
                uint32_t addr = As +
                    (warp_m * 64 + mf * 16 + (lane & 15)) * ROWB +
                    kk * 32 + (lane >> 4) * 16;
                ldm_x4(af[mf], addr);
            }
#pragma unroll
            for (int np = 0; np < 4; np++) {
                uint32_t rr[4];
                uint32_t addr = Bs +
                    (warp_n * 64 + np * 16 + ((lane >> 4) << 3) + (lane & 7)) * ROWB +
                    kk * 32 + ((lane >> 3) & 1) * 16;
                ldm_x4(rr, addr);
                bf[np * 2 + 0][0] = rr[0]; bf[np * 2 + 0][1] = rr[1];
                bf[np * 2 + 1][0] = rr[2]; bf[np * 2 + 1][1] = rr[3];
            }
#pragma unroll
            for (int mf = 0; mf < 4; mf++)
#pragma unroll
                for (int nf = 0; nf < 8; nf++)
                    mma_fp8(acc[mf][nf], af[mf], bf[nf]);
        }
    }

    // ---- epilogue: per-row sumexp (scale by 1/64) ----
    const int qid = lane >> 2;
    const int qlane = lane & 3;
#pragma unroll
    for (int mf = 0; mf < 4; mf++) {
#pragma unroll
        for (int h = 0; h < 2; h++) {
            int rl = warp_m * 64 + mf * 16 + qid + h * 8;
            int rg = row0 + rl;
            bool valid = rg < count;
            float s = 0.f;
#pragma unroll
            for (int nf = 0; nf < 8; nf++) {
                int cl = col0 + warp_n * 64 + nf * 8 + qlane * 2;
                if (cl < ncols)
                    s += __expf(acc[mf][nf][h * 2 + 0] * INV_BSCALE);
                if (cl + 1 < ncols)
                    s += __expf(acc[mf][nf][h * 2 + 1] * INV_BSCALE);
            }
            s += __shfl_xor_sync(0xffffffffu, s, 1);
            s += __shfl_xor_sync(0xffffffffu, s, 2);
            if (valid && qlane == 0) atomicAdd(&g_sumexp[stok[rl]], s);
        }
    }
}

// ---------------------------------------------------------------------------
// L4: exact fp32 target logit: g_tgt[t] = dot(x[t], logits[:, y[t]])
// ---------------------------------------------------------------------------
__global__ void k_tgt(const float* __restrict__ x,
                      const int* __restrict__ y,
                      const float* __restrict__ logits, int n, int vocab) {
    int warp = (blockIdx.x * blockDim.x + threadIdx.x) >> 5;
    int lane = threadIdx.x & 31;
    if (warp >= n) return;
    const int gy = y[warp];
    const float* xr = x + (size_t)warp * HID;
    float s = 0.f;
#pragma unroll 4
    for (int k = lane; k < HID; k += 32)
        s += xr[k] * logits[(size_t)k * vocab + gy];
#pragma unroll
    for (int m = 16; m; m >>= 1)
        s += __shfl_xor_sync(0xffffffffu, s, m);
    if (lane == 0) g_tgt[warp] = s;
}

// ---------------------------------------------------------------------------
// L5: finalize
// ---------------------------------------------------------------------------
__global__ void k_final(float* __restrict__ out, int n) {
    int t = blockIdx.x * blockDim.x + threadIdx.x;
    if (t >= n) return;
    out[t] = g_rownll[t] + logf(g_sumexp[t]) - g_tgt[t];
}

// ---------------------------------------------------------------------------
extern "C" void kernel_launch(void* const* d_in, const int* in_sizes, int n_in,
                              void* d_out, int out_size) {
    const float* x = (const float*)d_in[0];
    const int* y = (const int*)d_in[1];
    const float* Wc = (const float*)d_in[2];
    const float* logits = (const float*)d_in[3];
    float* out = (float*)d_out;

    int n = in_sizes[1];               // 4096
    int hidden = in_sizes[0] / n;      // 1024
    int vocab = in_sizes[3] / hidden;  // 50257

    cudaFuncSetAttribute(k_main_mma,
                         cudaFuncAttributeMaxDynamicSharedMemorySize, SMEM_DYN);

    // 0: B quantize (also zeros g_counts)
    k_convert_B<<<dim3((vocab + 31) / 32, hidden / 64), 256>>>(logits, vocab);
    // 1: cluster head + bucketing
    k_cluster_bucket<<<(n + 7) / 8, 256>>>(x, y, Wc, n);
    // 2: A quantize (bucketed)
    k_convert_x<<<dim3(n, NCL), 128>>>(x);
    // 3: main fp8 GEMM  (ncu profiled slot)
    dim3 grid((20000 + 255) / 256, (n + 127) / 128, NCL);
    k_main_mma<<<grid, 256, SMEM_DYN>>>(vocab);
    // 4: exact target logits
    k_tgt<<<(n + 7) / 8, 256>>>(x, y, logits, n, vocab);
    // 5: finalize
    k_final<<<(n + 255) / 256, 256>>>(out, n);
}